// round 2
// baseline (speedup 1.0000x reference)
#include <cuda_runtime.h>
#include <cstdint>
#include <math.h>

#define NB 8192
#define NNODE 32
#define DIN 128
#define TT 3

// ---------------- scratch (static device globals are allowed) ---------------
__device__ float g_hagg[NB * 384];       // [b][j*128+d]
__device__ float g_vtop[9 * DIN];        // [i*3+j][d] = sum_h W[i,d,h]*a_top[j,h]
__device__ float g_vbot[3 * DIN];        // [j][d]     = sum_h W[j,d,h]*a_bot[j,h]
__device__ int   g_mask_mode;            // 0=u8, 1=i32, 2=f32

typedef unsigned long long u64;
__device__ __forceinline__ u64 pack2(float lo, float hi) {
    u64 r; asm("mov.b64 %0, {%1,%2};" : "=l"(r) : "f"(lo), "f"(hi)); return r;
}
__device__ __forceinline__ u64 ffma2(u64 a, u64 b, u64 c) {
    u64 d; asm("fma.rn.f32x2 %0, %1, %2, %3;" : "=l"(d) : "l"(a), "l"(b), "l"(c)); return d;
}
__device__ __forceinline__ void unpack2(u64 v, float& lo, float& hi) {
    asm("mov.b64 {%0,%1}, %2;" : "=f"(lo), "=f"(hi) : "l"(v));
}
__device__ __forceinline__ float sel3(int j, float a, float b, float c) {
    return (j == 0) ? a : ((j == 1) ? b : c);
}
__device__ __forceinline__ float elu1(float x) { return x > 0.f ? x : expm1f(x); }

// ---------------- kernel S: sniff mask dtype --------------------------------
__global__ void k_sniff(const unsigned char* __restrict__ m) {
    if (threadIdx.x != 0 || blockIdx.x != 0) return;
    const uint32_t* w = (const uint32_t*)m;
    bool all01 = true, anyf = false;
    for (int i = 0; i < 256; i++) {
        uint32_t v = w[i];
        if (v == 0x3f800000u) anyf = true;
        if (v != 0u && v != 1u) all01 = false;
    }
    g_mask_mode = anyf ? 2 : (all01 ? 1 : 0);
}

// ---------------- kernel 0: v_top / v_bot precompute ------------------------
__global__ void k_precompute(const float* __restrict__ W, const float* __restrict__ a) {
    int v = blockIdx.x;          // 0..8 -> v_top(i*3+j), 9..11 -> v_bot(j)
    int d = threadIdx.x;         // 128 threads
    int i = (v < 9) ? (v / 3) : (v - 9);
    int j = (v < 9) ? (v % 3) : (v - 9);
    const float4* Wr = (const float4*)(W + (size_t)(i * DIN + d) * DIN);
    const float4* av = (const float4*)(a + j * 2 * DIN + ((v < 9) ? 0 : DIN));
    float s = 0.f;
#pragma unroll
    for (int hh = 0; hh < 32; hh++) {
        float4 w4 = Wr[hh];
        float4 a4 = av[hh];
        s += w4.x * a4.x + w4.y * a4.y + w4.z * a4.z + w4.w * a4.w;
    }
    if (v < 9) g_vtop[v * DIN + d] = s;
    else       g_vbot[(v - 9) * DIN + d] = s;
}

// ---------------- kernel 1: scores + factorized softmax + hagg --------------
// grid 2048 CTAs (4 b each), 128 threads (1 warp per b)
__global__ void k_main(const float* __restrict__ h, const unsigned char* __restrict__ mask) {
    extern __shared__ float smem[];
    float* h_sh  = smem;                        // [4][32][128]
    float* sn_sh = smem + 4 * NNODE * DIN;      // [4][96]  scores: j*31 + (n-1)
    float* w_sh  = sn_sh + 4 * 96;              // [4][96]  weights same layout
    unsigned char* m_sh = (unsigned char*)(w_sh + 4 * 96);  // [3][4][32]

    const int tid  = threadIdx.x;
    const int lane = tid & 31;
    const int wid  = tid >> 5;
    const int b0   = blockIdx.x * 4;

    // cooperative load h tile (4 b * 4096 floats, fully contiguous)
    {
        const float4* hg = (const float4*)(h + (size_t)b0 * NNODE * DIN);
        float4* hs = (float4*)h_sh;
#pragma unroll
        for (int r = 0; r < 32; r++) hs[tid + r * 128] = hg[tid + r * 128];
    }
    // mask tile: [t][b0..b0+3][0..31] -> 3*128 bytes in m_sh, dtype-adaptive
    if (tid < 96) {
        int t = tid >> 5, r = tid & 31;
        size_t base = (size_t)t * NB * NNODE + (size_t)b0 * NNODE + (size_t)r * 4;
        uint32_t packed;
        int mode = g_mask_mode;
        if (mode == 0) {
            packed = ((const uint32_t*)mask)[base >> 2];
        } else if (mode == 1) {
            const int* mi = (const int*)mask;
            packed =  (uint32_t)(mi[base]     != 0)
                   | ((uint32_t)(mi[base + 1] != 0) << 8)
                   | ((uint32_t)(mi[base + 2] != 0) << 16)
                   | ((uint32_t)(mi[base + 3] != 0) << 24);
        } else {
            const float* mf = (const float*)mask;
            packed =  (uint32_t)(mf[base]     != 0.f)
                   | ((uint32_t)(mf[base + 1] != 0.f) << 8)
                   | ((uint32_t)(mf[base + 2] != 0.f) << 16)
                   | ((uint32_t)(mf[base + 3] != 0.f) << 24);
        }
        ((uint32_t*)m_sh)[tid] = packed;
    }
    // per-lane slices of score vectors
    float4 vt[9], vb[3];
    {
        const float4* vt4 = (const float4*)g_vtop;
        const float4* vb4 = (const float4*)g_vbot;
#pragma unroll
        for (int k = 0; k < 9; k++) vt[k] = vt4[k * 32 + lane];
#pragma unroll
        for (int k = 0; k < 3; k++) vb[k] = vb4[k * 32 + lane];
    }
    __syncthreads();

    const int bi = wid;
    const float4* hb = (const float4*)(h_sh + bi * NNODE * DIN);
    float* snb = sn_sh + bi * 96;
    float* wb  = w_sh + bi * 96;

    // ---- self scores ss[i*3+j] ----
    float ss[9];
    {
        float4 hv = hb[lane];
#pragma unroll
        for (int k = 0; k < 9; k++) {
            float p = hv.x * vt[k].x + hv.y * vt[k].y + hv.z * vt[k].z + hv.w * vt[k].w;
#pragma unroll
            for (int o = 16; o > 0; o >>= 1) p += __shfl_xor_sync(0xffffffffu, p, o);
            ss[k] = p;
        }
    }
    float M1 = ss[0];
#pragma unroll
    for (int k = 1; k < 9; k++) M1 = fmaxf(M1, ss[k]);
    float E0 = expf(ss[0] - M1) + expf(ss[3] - M1) + expf(ss[6] - M1);
    float E1 = expf(ss[1] - M1) + expf(ss[4] - M1) + expf(ss[7] - M1);
    float E2 = expf(ss[2] - M1) + expf(ss[5] - M1) + expf(ss[8] - M1);

    // ---- neighbor scores sn[j][n-1] ----
    for (int n = 1; n < NNODE; n++) {
        float4 hv = hb[n * 32 + lane];
        float p0 = hv.x * vb[0].x + hv.y * vb[0].y + hv.z * vb[0].z + hv.w * vb[0].w;
        float p1 = hv.x * vb[1].x + hv.y * vb[1].y + hv.z * vb[1].z + hv.w * vb[1].w;
        float p2 = hv.x * vb[2].x + hv.y * vb[2].y + hv.z * vb[2].z + hv.w * vb[2].w;
#pragma unroll
        for (int o = 16; o > 0; o >>= 1) {
            p0 += __shfl_xor_sync(0xffffffffu, p0, o);
            p1 += __shfl_xor_sync(0xffffffffu, p1, o);
            p2 += __shfl_xor_sync(0xffffffffu, p2, o);
        }
        if (lane == 0) {
            snb[n - 1]      = p0;
            snb[31 + n - 1] = p1;
            snb[62 + n - 1] = p2;
        }
    }
    __syncwarp();

    // ---- masked, group-wise factorized softmax -> weights w[j][n-1] ----
#pragma unroll
    for (int g = 0; g < 2; g++) {
        const int cnt = g ? 16 : 15;
        const int nodeOff = g ? 16 : 1;
        const int wOff = g ? 15 : 0;
        const int tot = 3 * cnt;
        int p1i = lane, p2i = lane + 32;
        float y1 = -INFINITY, y2 = -INFINITY;
        int j1 = 0, j2 = 0, nn1 = 0, nn2 = 0, v1 = 0, v2 = 0;
        if (p1i < tot) {
            j1 = p1i / cnt; nn1 = p1i % cnt;
            v1 = (m_sh[j1 * 128 + bi * 32 + nodeOff + nn1] == 0);
            if (v1) y1 = snb[j1 * 31 + wOff + nn1];
        }
        if (p2i < tot) {
            j2 = p2i / cnt; nn2 = p2i % cnt;
            v2 = (m_sh[j2 * 128 + bi * 32 + nodeOff + nn2] == 0);
            if (v2) y2 = snb[j2 * 31 + wOff + nn2];
        }
        float M2 = fmaxf(y1, y2);
#pragma unroll
        for (int o = 16; o > 0; o >>= 1) M2 = fmaxf(M2, __shfl_xor_sync(0xffffffffu, M2, o));
        float t1 = v1 ? sel3(j1, E0, E1, E2) * expf(y1 - M2) : 0.f;
        float t2 = v2 ? sel3(j2, E0, E1, E2) * expf(y2 - M2) : 0.f;
        float Z = t1 + t2;
#pragma unroll
        for (int o = 16; o > 0; o >>= 1) Z += __shfl_xor_sync(0xffffffffu, Z, o);
        float inv = (Z > 0.f) ? (1.f / Z) : 0.f;   // all-masked group -> zeros (matches ref)
        if (p1i < tot) wb[j1 * 31 + wOff + nn1] = t1 * inv;
        if (p2i < tot) wb[j2 * 31 + wOff + nn2] = t2 * inv;
    }
    __syncwarp();

    // ---- hagg[j][:] = mask_self[j]*h_self + sum_n w[j][n]*h[n] ----
    float4 a0, a1, a2;
    {
        float4 hv = hb[lane];
        float m0 = m_sh[bi * 32]       ? 1.f : 0.f;
        float m1 = m_sh[128 + bi * 32] ? 1.f : 0.f;
        float m2 = m_sh[256 + bi * 32] ? 1.f : 0.f;
        a0 = make_float4(m0 * hv.x, m0 * hv.y, m0 * hv.z, m0 * hv.w);
        a1 = make_float4(m1 * hv.x, m1 * hv.y, m1 * hv.z, m1 * hv.w);
        a2 = make_float4(m2 * hv.x, m2 * hv.y, m2 * hv.z, m2 * hv.w);
    }
#pragma unroll
    for (int n = 1; n < NNODE; n++) {
        float4 hv = hb[n * 32 + lane];
        float w0 = wb[n - 1], w1 = wb[31 + n - 1], w2 = wb[62 + n - 1];
        a0.x += w0 * hv.x; a0.y += w0 * hv.y; a0.z += w0 * hv.z; a0.w += w0 * hv.w;
        a1.x += w1 * hv.x; a1.y += w1 * hv.y; a1.z += w1 * hv.z; a1.w += w1 * hv.w;
        a2.x += w2 * hv.x; a2.y += w2 * hv.y; a2.z += w2 * hv.z; a2.w += w2 * hv.w;
    }
    float4* og = (float4*)(g_hagg + (size_t)(b0 + bi) * 384);
    og[lane]      = a0;
    og[32 + lane] = a1;
    og[64 + lane] = a2;
}

// ---------------- kernel 2: out = elu(hagg @ Wstack), FFMA2 -----------------
// grid (128, 4): 64 b-rows x 32 h-cols per CTA, 256 threads, 8 outputs/thread
__global__ void k_gemm(const float* __restrict__ W, float* __restrict__ out) {
    extern __shared__ float smem[];
    float* W_sh = smem;               // [384][32]
    float* A_sh = smem + 384 * 32;    // [64][128] jd-chunk
    const int tid = threadIdx.x;
    const int bT = blockIdx.x * 64;
    const int hT = blockIdx.y * 32;

    // Wstack[jd][h] = W[j][d][h] -> global index jd*128 + h
    for (int idx = tid; idx < 384 * 32; idx += 256) {
        int jd = idx >> 5, hh = idx & 31;
        W_sh[idx] = W[(size_t)jd * 128 + hT + hh];
    }

    const int hg = tid & 7;   // 8 groups of 4 h
    const int bg = tid >> 3;  // 32 groups of 2 b
    u64 acc00 = 0, acc01 = 0, acc10 = 0, acc11 = 0;  // 0ull == {+0.f,+0.f}

    for (int c = 0; c < 3; c++) {
        __syncthreads();
        const float4* Ag = (const float4*)(g_hagg + (size_t)bT * 384 + c * 128);
        float4* As4 = (float4*)A_sh;
#pragma unroll
        for (int r8 = 0; r8 < 8; r8++) {
            int idx = tid + r8 * 256;
            int r = idx >> 5, cc = idx & 31;
            As4[idx] = Ag[(size_t)r * 96 + cc];
        }
        __syncthreads();
        const float* Ar0 = A_sh + (bg * 2) * 128;
        const float* Ar1 = Ar0 + 128;
        const ulonglong2* Wv = (const ulonglong2*)W_sh;
#pragma unroll 8
        for (int k = 0; k < 128; k++) {
            float av0 = Ar0[k], av1 = Ar1[k];
            u64 a0p = pack2(av0, av0);
            u64 a1p = pack2(av1, av1);
            ulonglong2 w = Wv[(size_t)(c * 128 + k) * 8 + hg];
            acc00 = ffma2(a0p, w.x, acc00);
            acc01 = ffma2(a0p, w.y, acc01);
            acc10 = ffma2(a1p, w.x, acc10);
            acc11 = ffma2(a1p, w.y, acc11);
        }
    }
    float r00, r01, r02, r03, r10, r11, r12, r13;
    unpack2(acc00, r00, r01); unpack2(acc01, r02, r03);
    unpack2(acc10, r10, r11); unpack2(acc11, r12, r13);
    int b0 = bT + bg * 2;
    float4* o0 = (float4*)(out + (size_t)b0 * 128 + hT + hg * 4);
    float4* o1 = (float4*)(out + (size_t)(b0 + 1) * 128 + hT + hg * 4);
    *o0 = make_float4(elu1(r00), elu1(r01), elu1(r02), elu1(r03));
    *o1 = make_float4(elu1(r10), elu1(r11), elu1(r12), elu1(r13));
}

// ---------------- launcher ---------------------------------------------------
extern "C" void kernel_launch(void* const* d_in, const int* in_sizes, int n_in,
                              void* d_out, int out_size) {
    // size-based binding: h=33554432, mask=786432, W=49152, a=768
    const float* h = nullptr;
    const unsigned char* mask = nullptr;
    const float* W = nullptr;
    const float* a = nullptr;
    for (int i = 0; i < n_in; i++) {
        int s = in_sizes[i];
        if      (s == NB * NNODE * DIN)      h = (const float*)d_in[i];
        else if (s == TT * NB * NNODE)       mask = (const unsigned char*)d_in[i];
        else if (s == TT * DIN * DIN)        W = (const float*)d_in[i];
        else if (s == TT * 2 * DIN)          a = (const float*)d_in[i];
    }
    if (!h)    h = (const float*)d_in[0];
    if (!mask) mask = (const unsigned char*)d_in[1];
    if (!W)    W = (const float*)d_in[n_in - 2];
    if (!a)    a = (const float*)d_in[n_in - 1];
    float* out = (float*)d_out;

    const int smem_main = (4 * NNODE * DIN + 4 * 96 * 2) * 4 + 3 * 4 * NNODE;  // 68992
    const int smem_gemm = (384 * 32 + 64 * 128) * 4;                            // 81920
    cudaFuncSetAttribute(k_main, cudaFuncAttributeMaxDynamicSharedMemorySize, smem_main);
    cudaFuncSetAttribute(k_gemm, cudaFuncAttributeMaxDynamicSharedMemorySize, smem_gemm);

    k_sniff<<<1, 1>>>(mask);
    k_precompute<<<12, 128>>>(W, a);
    k_main<<<NB / 4, 128, smem_main>>>(h, mask);
    k_gemm<<<dim3(NB / 64, 4), 256, smem_gemm>>>(W, out);
}

// round 3
// speedup vs baseline: 1.5329x; 1.5329x over previous
#include <cuda_runtime.h>
#include <cstdint>
#include <math.h>

#define NB 8192
#define NNODE 32
#define DIN 128
#define TT 3

// ---------------- scratch -----------------------------------------------------
__device__ __align__(16) float g_hagg[NB * 384];   // [b][j*128+d]
__device__ __align__(16) float g_vtop[9 * DIN];
__device__ __align__(16) float g_vbot[3 * DIN];
__device__ int g_mask_mode;                        // 0=u8, 1=i32, 2=f32

typedef unsigned long long u64;
__device__ __forceinline__ u64 pack2(float lo, float hi) {
    u64 r; asm("mov.b64 %0, {%1,%2};" : "=l"(r) : "f"(lo), "f"(hi)); return r;
}
__device__ __forceinline__ u64 ffma2(u64 a, u64 b, u64 c) {
    u64 d; asm("fma.rn.f32x2 %0, %1, %2, %3;" : "=l"(d) : "l"(a), "l"(b), "l"(c)); return d;
}
__device__ __forceinline__ void unpack2(u64 v, float& lo, float& hi) {
    asm("mov.b64 {%0,%1}, %2;" : "=f"(lo), "=f"(hi) : "l"(v));
}
__device__ __forceinline__ float sel3(int j, float a, float b, float c) {
    return (j == 0) ? a : ((j == 1) ? b : c);
}
__device__ __forceinline__ float elu1(float x) { return x > 0.f ? x : expm1f(x); }
__device__ __forceinline__ float dot4(float4 a, float4 b) {
    return a.x * b.x + a.y * b.y + a.z * b.z + a.w * b.w;
}

// ---------------- kernel S: sniff mask dtype ----------------------------------
__global__ void k_sniff(const unsigned char* __restrict__ m) {
    if (threadIdx.x != 0 || blockIdx.x != 0) return;
    const uint32_t* w = (const uint32_t*)m;
    bool all01 = true, anyf = false;
    for (int i = 0; i < 256; i++) {
        uint32_t v = w[i];
        if (v == 0x3f800000u) anyf = true;
        if (v != 0u && v != 1u) all01 = false;
    }
    g_mask_mode = anyf ? 2 : (all01 ? 1 : 0);
}

// ---------------- kernel 0: v_top / v_bot precompute --------------------------
__global__ void k_precompute(const float* __restrict__ W, const float* __restrict__ a) {
    int v = blockIdx.x;
    int d = threadIdx.x;
    int i = (v < 9) ? (v / 3) : (v - 9);
    int j = (v < 9) ? (v % 3) : (v - 9);
    const float4* Wr = (const float4*)(W + (size_t)(i * DIN + d) * DIN);
    const float4* av = (const float4*)(a + j * 2 * DIN + ((v < 9) ? 0 : DIN));
    float s = 0.f;
#pragma unroll
    for (int hh = 0; hh < 32; hh++) s += dot4(Wr[hh], av[hh]);
    if (v < 9) g_vtop[v * DIN + d] = s;
    else       g_vbot[(v - 9) * DIN + d] = s;
}

// ---------------- kernel 1: fused scores + softmax + aggregation --------------
// grid 2048 CTAs (4 b each), 128 threads
// smem (floats): h_sh 16384 | psn 6144 | sn_sh 384 | ss_sh 40 | w_sh 384 | mask 96
__global__ void k_main(const float* __restrict__ h, const unsigned char* __restrict__ mask) {
    extern __shared__ float smem[];
    float* h_sh  = smem;                 // [128 rows][128 d]
    float* psn   = smem + 16384;         // [(row*3+j)*16 + lane16]
    float* sn_sh = smem + 22528;         // [b*96 + j*31 + (n-1)]
    float* ss_sh = smem + 22912;         // [b*9 + k]
    float* w_sh  = smem + 22952;         // [b*96 + j*31 + (n-1)]
    unsigned char* m_sh = (unsigned char*)(smem + 23336);  // [t*128 + b*32 + n]

    const int tid  = threadIdx.x;
    const int lane = tid & 31;
    const int wid  = tid >> 5;
    const int b0   = blockIdx.x * 4;

    // mask tile, dtype-adaptive
    if (tid < 96) {
        int t = tid >> 5, r = tid & 31;
        size_t base = (size_t)t * NB * NNODE + (size_t)b0 * NNODE + (size_t)r * 4;
        uint32_t packed;
        int mode = g_mask_mode;
        if (mode == 0) {
            packed = ((const uint32_t*)mask)[base >> 2];
        } else if (mode == 1) {
            const int* mi = (const int*)mask;
            packed =  (uint32_t)(mi[base]     != 0)
                   | ((uint32_t)(mi[base + 1] != 0) << 8)
                   | ((uint32_t)(mi[base + 2] != 0) << 16)
                   | ((uint32_t)(mi[base + 3] != 0) << 24);
        } else {
            const float* mf = (const float*)mask;
            packed =  (uint32_t)(mf[base]     != 0.f)
                   | ((uint32_t)(mf[base + 1] != 0.f) << 8)
                   | ((uint32_t)(mf[base + 2] != 0.f) << 16)
                   | ((uint32_t)(mf[base + 3] != 0.f) << 24);
        }
        ((uint32_t*)m_sh)[tid] = packed;
    }

    // per-lane d4-slice of the 3 neighbor score vectors
    float4 vb[3];
    {
        const float4* vb4 = (const float4*)g_vbot;
#pragma unroll
        for (int k = 0; k < 3; k++) vb[k] = vb4[k * 32 + lane];
    }

    // ---- phase 0: load h tile + per-row partial neighbor scores ----
    {
        const float4* hg = (const float4*)(h + (size_t)b0 * NNODE * DIN);
        float4* hs = (float4*)h_sh;
        const int rowq = tid >> 5;
#pragma unroll 8
        for (int r = 0; r < 32; r++) {
            float4 hv = hg[tid + r * 128];
            hs[tid + r * 128] = hv;
            int row = rowq + r * 4;
#pragma unroll
            for (int j = 0; j < 3; j++) {
                float p = dot4(hv, vb[j]);
                p += __shfl_xor_sync(0xffffffffu, p, 16);
                if (lane < 16) psn[(row * 3 + j) * 16 + lane] = p;
            }
        }
    }
    __syncthreads();

    // ---- phase 1: reduce partials -> sn_sh; serial self-score dots -> ss_sh ----
    {
        int n = tid & 31, b = tid >> 5;
#pragma unroll
        for (int j = 0; j < 3; j++) {
            int base = (tid * 3 + j) * 16;
            float s = 0.f;
#pragma unroll
            for (int k = 0; k < 16; k++) s += psn[base + ((k + tid) & 15)];
            if (n) sn_sh[b * 96 + j * 31 + (n - 1)] = s;
        }
        if (tid < 36) {
            int b = tid / 9, k9 = tid % 9;
            const float4* hb4 = (const float4*)(h_sh + b * NNODE * DIN);  // row n=0
            const float4* vt4 = (const float4*)g_vtop + k9 * 32;
            float p = 0.f;
#pragma unroll
            for (int s = 0; s < 32; s++) {
                int x = (s + tid) & 31;
                p += dot4(hb4[x], vt4[x]);
            }
            ss_sh[b * 9 + k9] = p;
        }
    }
    __syncthreads();

    // ---- phase 2: per-warp masked factorized softmax (warp wid -> b = b0+wid) --
    const int bi = wid;
    const float4* hb = (const float4*)(h_sh + bi * NNODE * DIN);
    float* snb = sn_sh + bi * 96;
    float* wb  = w_sh + bi * 96;

    float ss[9];
#pragma unroll
    for (int k = 0; k < 9; k++) ss[k] = ss_sh[bi * 9 + k];
    float M1 = ss[0];
#pragma unroll
    for (int k = 1; k < 9; k++) M1 = fmaxf(M1, ss[k]);
    float E0 = expf(ss[0] - M1) + expf(ss[3] - M1) + expf(ss[6] - M1);
    float E1 = expf(ss[1] - M1) + expf(ss[4] - M1) + expf(ss[7] - M1);
    float E2 = expf(ss[2] - M1) + expf(ss[5] - M1) + expf(ss[8] - M1);

#pragma unroll
    for (int g = 0; g < 2; g++) {
        const int cnt = g ? 16 : 15;
        const int nodeOff = g ? 16 : 1;
        const int wOff = g ? 15 : 0;
        const int tot = 3 * cnt;
        int p1i = lane, p2i = lane + 32;
        float y1 = -INFINITY, y2 = -INFINITY;
        int j1 = 0, j2 = 0, nn1 = 0, nn2 = 0, v1 = 0, v2 = 0;
        if (p1i < tot) {
            j1 = p1i / cnt; nn1 = p1i % cnt;
            v1 = (m_sh[j1 * 128 + bi * 32 + nodeOff + nn1] == 0);
            if (v1) y1 = snb[j1 * 31 + wOff + nn1];
        }
        if (p2i < tot) {
            j2 = p2i / cnt; nn2 = p2i % cnt;
            v2 = (m_sh[j2 * 128 + bi * 32 + nodeOff + nn2] == 0);
            if (v2) y2 = snb[j2 * 31 + wOff + nn2];
        }
        float M2 = fmaxf(y1, y2);
#pragma unroll
        for (int o = 16; o > 0; o >>= 1) M2 = fmaxf(M2, __shfl_xor_sync(0xffffffffu, M2, o));
        float t1 = v1 ? sel3(j1, E0, E1, E2) * expf(y1 - M2) : 0.f;
        float t2 = v2 ? sel3(j2, E0, E1, E2) * expf(y2 - M2) : 0.f;
        float Z = t1 + t2;
#pragma unroll
        for (int o = 16; o > 0; o >>= 1) Z += __shfl_xor_sync(0xffffffffu, Z, o);
        float inv = (Z > 0.f) ? (1.f / Z) : 0.f;
        if (p1i < tot) wb[j1 * 31 + wOff + nn1] = t1 * inv;
        if (p2i < tot) wb[j2 * 31 + wOff + nn2] = t2 * inv;
    }
    __syncwarp();

    // ---- phase 3: aggregation ----
    float4 a0, a1, a2;
    {
        float4 hv = hb[lane];
        float m0 = m_sh[bi * 32]       ? 1.f : 0.f;
        float m1 = m_sh[128 + bi * 32] ? 1.f : 0.f;
        float m2 = m_sh[256 + bi * 32] ? 1.f : 0.f;
        a0 = make_float4(m0 * hv.x, m0 * hv.y, m0 * hv.z, m0 * hv.w);
        a1 = make_float4(m1 * hv.x, m1 * hv.y, m1 * hv.z, m1 * hv.w);
        a2 = make_float4(m2 * hv.x, m2 * hv.y, m2 * hv.z, m2 * hv.w);
    }
#pragma unroll
    for (int n = 1; n < NNODE; n++) {
        float4 hv = hb[n * 32 + lane];
        float w0 = wb[n - 1], w1 = wb[31 + n - 1], w2 = wb[62 + n - 1];
        a0.x += w0 * hv.x; a0.y += w0 * hv.y; a0.z += w0 * hv.z; a0.w += w0 * hv.w;
        a1.x += w1 * hv.x; a1.y += w1 * hv.y; a1.z += w1 * hv.z; a1.w += w1 * hv.w;
        a2.x += w2 * hv.x; a2.y += w2 * hv.y; a2.z += w2 * hv.z; a2.w += w2 * hv.w;
    }
    float4* og = (float4*)(g_hagg + (size_t)(b0 + bi) * 384);
    og[lane]      = a0;
    og[32 + lane] = a1;
    og[64 + lane] = a2;
}

// ---------------- kernel 2: register-tiled SGEMM + ELU ------------------------
// C[8192,128] = g_hagg[8192,384] @ Wstack[384,128]; CTA 64x128, thread 4x8
#define APAD 36
__global__ void __launch_bounds__(256) k_gemm(const float* __restrict__ W,
                                              float* __restrict__ out) {
    __shared__ float Ash[64][APAD];      // [m][k-chunk 32], padded
    __shared__ float Bsh[32][128];       // [k][n]
    const int tid = threadIdx.x;
    const int m0 = blockIdx.x * 64;
    const int tn = tid & 15;             // 16 n-groups * 8
    const int tm = tid >> 4;             // 16 m-groups * 4
    const float* Ag = g_hagg + (size_t)m0 * 384;

    float4 avp[2], bvp[4];
    u64 acc[4][4];
#pragma unroll
    for (int mi = 0; mi < 4; mi++)
#pragma unroll
        for (int nj = 0; nj < 4; nj++) acc[mi][nj] = 0ull;

    // prefetch chunk 0
    {
        const int c = 0;
#pragma unroll
        for (int i = 0; i < 2; i++) {
            int idx = tid + i * 256, m = idx >> 3, f = idx & 7;
            avp[i] = ((const float4*)(Ag + (size_t)m * 384 + c * 32))[f];
        }
#pragma unroll
        for (int i = 0; i < 4; i++) {
            int idx = tid + i * 256, k = idx >> 5, f = idx & 31;
            bvp[i] = ((const float4*)(W + (size_t)(c * 32 + k) * 128))[f];
        }
    }

    for (int c = 0; c < 12; c++) {
        // store prefetched chunk
#pragma unroll
        for (int i = 0; i < 2; i++) {
            int idx = tid + i * 256, m = idx >> 3, f = idx & 7;
            Ash[m][f * 4 + 0] = avp[i].x; Ash[m][f * 4 + 1] = avp[i].y;
            Ash[m][f * 4 + 2] = avp[i].z; Ash[m][f * 4 + 3] = avp[i].w;
        }
#pragma unroll
        for (int i = 0; i < 4; i++) {
            int idx = tid + i * 256, k = idx >> 5, f = idx & 31;
            ((float4*)Bsh[k])[f] = bvp[i];
        }
        __syncthreads();
        // prefetch next chunk
        if (c < 11) {
            const int cn = c + 1;
#pragma unroll
            for (int i = 0; i < 2; i++) {
                int idx = tid + i * 256, m = idx >> 3, f = idx & 7;
                avp[i] = ((const float4*)(Ag + (size_t)m * 384 + cn * 32))[f];
            }
#pragma unroll
            for (int i = 0; i < 4; i++) {
                int idx = tid + i * 256, k = idx >> 5, f = idx & 31;
                bvp[i] = ((const float4*)(W + (size_t)(cn * 32 + k) * 128))[f];
            }
        }
        // compute
#pragma unroll
        for (int k = 0; k < 32; k++) {
            float a0 = Ash[tm * 4 + 0][k];
            float a1 = Ash[tm * 4 + 1][k];
            float a2 = Ash[tm * 4 + 2][k];
            float a3 = Ash[tm * 4 + 3][k];
            ulonglong2 b01 = ((const ulonglong2*)Bsh[k])[tn * 2];
            ulonglong2 b23 = ((const ulonglong2*)Bsh[k])[tn * 2 + 1];
            u64 am0 = pack2(a0, a0), am1 = pack2(a1, a1);
            u64 am2 = pack2(a2, a2), am3 = pack2(a3, a3);
            acc[0][0] = ffma2(am0, b01.x, acc[0][0]);
            acc[0][1] = ffma2(am0, b01.y, acc[0][1]);
            acc[0][2] = ffma2(am0, b23.x, acc[0][2]);
            acc[0][3] = ffma2(am0, b23.y, acc[0][3]);
            acc[1][0] = ffma2(am1, b01.x, acc[1][0]);
            acc[1][1] = ffma2(am1, b01.y, acc[1][1]);
            acc[1][2] = ffma2(am1, b23.x, acc[1][2]);
            acc[1][3] = ffma2(am1, b23.y, acc[1][3]);
            acc[2][0] = ffma2(am2, b01.x, acc[2][0]);
            acc[2][1] = ffma2(am2, b01.y, acc[2][1]);
            acc[2][2] = ffma2(am2, b23.x, acc[2][2]);
            acc[2][3] = ffma2(am2, b23.y, acc[2][3]);
            acc[3][0] = ffma2(am3, b01.x, acc[3][0]);
            acc[3][1] = ffma2(am3, b01.y, acc[3][1]);
            acc[3][2] = ffma2(am3, b23.x, acc[3][2]);
            acc[3][3] = ffma2(am3, b23.y, acc[3][3]);
        }
        if (c < 11) __syncthreads();
    }

    // epilogue: ELU + store
#pragma unroll
    for (int mi = 0; mi < 4; mi++) {
        int m = m0 + tm * 4 + mi;
        float x0, x1, x2, x3, x4, x5, x6, x7;
        unpack2(acc[mi][0], x0, x1); unpack2(acc[mi][1], x2, x3);
        unpack2(acc[mi][2], x4, x5); unpack2(acc[mi][3], x6, x7);
        float4* o = (float4*)(out + (size_t)m * 128 + tn * 8);
        o[0] = make_float4(elu1(x0), elu1(x1), elu1(x2), elu1(x3));
        o[1] = make_float4(elu1(x4), elu1(x5), elu1(x6), elu1(x7));
    }
}

// ---------------- launcher ----------------------------------------------------
extern "C" void kernel_launch(void* const* d_in, const int* in_sizes, int n_in,
                              void* d_out, int out_size) {
    const float* h = nullptr;
    const unsigned char* mask = nullptr;
    const float* W = nullptr;
    const float* a = nullptr;
    for (int i = 0; i < n_in; i++) {
        int s = in_sizes[i];
        if      (s == NB * NNODE * DIN) h = (const float*)d_in[i];
        else if (s == TT * NB * NNODE)  mask = (const unsigned char*)d_in[i];
        else if (s == TT * DIN * DIN)   W = (const float*)d_in[i];
        else if (s == TT * 2 * DIN)     a = (const float*)d_in[i];
    }
    if (!h)    h = (const float*)d_in[0];
    if (!mask) mask = (const unsigned char*)d_in[1];
    if (!W)    W = (const float*)d_in[n_in - 2];
    if (!a)    a = (const float*)d_in[n_in - 1];
    float* out = (float*)d_out;

    const int smem_main = 23432 * 4;   // 93728 bytes
    cudaFuncSetAttribute(k_main, cudaFuncAttributeMaxDynamicSharedMemorySize, smem_main);

    k_sniff<<<1, 1>>>(mask);
    k_precompute<<<12, 128>>>(W, a);
    k_main<<<NB / 4, 128, smem_main>>>(h, mask);
    k_gemm<<<NB / 64, 256>>>(W, out);
}